// round 15
// baseline (speedup 1.0000x reference)
#include <cuda_runtime.h>
#include <cstdint>

// RipsH1 edge-length gather — FINAL (R4 configuration, unchanged).
// Measured band of this exact binary across 6 runs:
//   35.3 / 35.7 / 36.4 / 36.9 / 37.0 / 37.3 us  (mean ~36.4, sigma ~0.75)
//
// Flat distance list, D = e0 + 2*e1:
//   t <  e0 : (ia, ib) = verts0 row t
//   t >= e0 : (ia, ib) = ((int2*)verts1)[t - e0]
//   out[t]  = || pts[ia] - pts[ib] ||      (8-dim)
// (verts1 row j = [a0,b0,a1,b1]; out layout [deaths ++ dgm1-rowmajor] makes
//  the flat output index equal t exactly.)
//
// Evidence trail (R2-R14):
// - 2 lanes per distance: lane h owns float4 half h of each point; both 16B
//   halves of a 32B-aligned row share one sector -> ONE l1tex wavefront per
//   point (2/distance = structural minimum). R2->R3: 49.9 -> 39.6us.
// - U=4 distances per lane-pair, index loads then gathers front-batched
//   (8 independent LDG.128/lane). U-sweep: U=2 37.3, U=4 35.3, U=8 39.7us.
// - Natural regs (41) / 56% occ: occupancy swept 33-87%, zero sensitivity.
// - Cache ops (.cg on streams AND gathers): measured neutral — the L1% is
//   sector/replay processing throughput, not fill overhead.
// - Replay model: 16 lines per gather LDG.128 at ~2.07 cyc/wf replay rate
//   -> 56-58K cyc/SM floor vs 67K measured = 87-93% of floor. Shifting to
//   the 1.0 cyc/wf cross-LDG rate needs >=8 lanes/point, which costs a
//   3-level shfl tree (24x more SHFL warp-instrs on the same MIO pipe) —
//   modeled net-negative. 2-lane pair + 1 shfl is the joint optimum.
// - Rejected on model: TMA tile::gather4 (128B/request vs ~46cyc/request
//   service cost -> ~10x regression risk; LTS cap is path-independent),
//   smem two-pass binning (+80MB stream > gather savings), LDG.64/.32
//   splits (same wavefronts or more shfl), index dedup (same lines).

static constexpr int DIM_F4   = 2;      // 8 floats = 2 float4
static constexpr int IDX_MASK = 0xFFFF; // N_POINTS = 65536 (power of two)
static constexpr int U        = 4;      // distances per lane-pair
static constexpr int DIST_PER_WARP = 16 * U;  // 64

__global__ __launch_bounds__(256)
void rips_pair_u4_kernel(const float4* __restrict__ pts,
                         const int2* __restrict__ v0,   // e0 rows of 2 i32
                         const int2* __restrict__ v1p,  // verts1 as 2*e1 int2 pairs
                         float* __restrict__ out,
                         int e0, int total) {           // total = e0 + 2*e1
    const int gtid = blockIdx.x * blockDim.x + threadIdx.x;
    const int warp = gtid >> 5;
    const int lane = gtid & 31;
    const int pair = lane >> 1;   // 0..15
    const int h    = lane & 1;    // float4 half owned by this lane

    const int base = warp * DIST_PER_WARP + pair;

    // ---- phase 1: index loads (batched) ----
    int t[U], ia[U], ib[U];
    bool valid[U];
#pragma unroll
    for (int u = 0; u < U; u++) {
        int tt = base + u * 16;
        valid[u] = (tt < total);
        tt = valid[u] ? tt : (total - 1);      // clamp -> safe, converged
        t[u] = tt;
        const int2 p = (tt < e0) ? __ldg(v0 + tt)
                                 : __ldg(v1p + (tt - e0));
        ia[u] = p.x & IDX_MASK;
        ib[u] = p.y & IDX_MASK;
    }

    // ---- phase 2: gathers (batched; 8 independent LDG.128 in flight) ----
    float4 a[U], b[U];
#pragma unroll
    for (int u = 0; u < U; u++) {
        a[u] = __ldg(pts + ia[u] * DIM_F4 + h);
        b[u] = __ldg(pts + ib[u] * DIM_F4 + h);
    }

    // ---- phase 3: math + pair-combine + store ----
#pragma unroll
    for (int u = 0; u < U; u++) {
        float dx, s;
        dx = a[u].x - b[u].x; s = dx * dx;
        dx = a[u].y - b[u].y; s = fmaf(dx, dx, s);
        dx = a[u].z - b[u].z; s = fmaf(dx, dx, s);
        dx = a[u].w - b[u].w; s = fmaf(dx, dx, s);
        s += __shfl_xor_sync(0xFFFFFFFF, s, 1);
        if (valid[u] && h == 0)
            out[t[u]] = sqrtf(s);
    }
}

extern "C" void kernel_launch(void* const* d_in, const int* in_sizes, int n_in,
                              void* d_out, int out_size) {
    const float4* pts = (const float4*)d_in[0];
    const int2*   v0  = (const int2*)d_in[1];
    const int2*   v1p = (const int2*)d_in[2];
    float*        out = (float*)d_out;

    const int e0 = in_sizes[1] / 2;          // verts0 rows
    const int e1 = in_sizes[2] / 4;          // verts1 rows
    const int total = e0 + 2 * e1;           // flat distance count

    const int nwarps  = (total + DIST_PER_WARP - 1) / DIST_PER_WARP;
    const int threads = 256;
    const int blocks  = (nwarps * 32 + threads - 1) / threads;
    rips_pair_u4_kernel<<<blocks, threads>>>(pts, v0, v1p, out, e0, total);
}

// round 16
// speedup vs baseline: 1.0141x; 1.0141x over previous
#include <cuda_runtime.h>
#include <cstdint>

// RipsH1 edge-length gather — FINAL (R4 configuration, unchanged).
// Measured band of this exact binary across 7 runs:
//   35.3 / 35.7 / 36.4 / 36.9 / 36.9 / 37.0 / 37.3 us (mean 36.5, sigma 0.7)
//
// Flat distance list, D = e0 + 2*e1:
//   t <  e0 : (ia, ib) = verts0 row t
//   t >= e0 : (ia, ib) = ((int2*)verts1)[t - e0]
//   out[t]  = || pts[ia] - pts[ib] ||      (8-dim)
// (verts1 row j = [a0,b0,a1,b1]; out layout [deaths ++ dgm1-rowmajor] makes
//  the flat output index equal t exactly.)
//
// Evidence trail (R2-R15):
// - 2 lanes per distance: lane h owns float4 half h of each point; both 16B
//   halves of a 32B-aligned row share one sector -> ONE l1tex wavefront per
//   point (2/distance = structural minimum). R2->R3: 49.9 -> 39.6us.
// - U=4 distances per lane-pair, index loads then gathers front-batched
//   (8 independent LDG.128/lane). U-sweep: U=2 37.3, U=4 35.3, U=8 39.7us.
// - Natural regs (41) / 56% occ: occupancy swept 33-87%, zero sensitivity.
// - Cache ops (.cg on streams AND gathers): measured neutral — the L1% is
//   sector/replay processing throughput, not fill overhead.
// - Replay invariant: total random lines per distance is fixed at 2; the
//   within-LDG replay model (1 + 2.07*(nL-1) cyc per LDG) is arrangement-
//   independent for fixed total lines — 4-lane/2-level-shfl variants are
//   exactly neutral, deeper splits go negative on added SHFL traffic.
// - Rejected on model: TMA tile::gather4 (tiny 128B requests vs per-request
//   service cost; LTS cap path-independent), smem two-pass binning (+80MB
//   stream > gather savings), index dedup (same lines; issue not binding).
// - Operating point: ~90% of the l1tex uniform-random-gather floor.

static constexpr int DIM_F4   = 2;      // 8 floats = 2 float4
static constexpr int IDX_MASK = 0xFFFF; // N_POINTS = 65536 (power of two)
static constexpr int U        = 4;      // distances per lane-pair
static constexpr int DIST_PER_WARP = 16 * U;  // 64

__global__ __launch_bounds__(256)
void rips_pair_u4_kernel(const float4* __restrict__ pts,
                         const int2* __restrict__ v0,   // e0 rows of 2 i32
                         const int2* __restrict__ v1p,  // verts1 as 2*e1 int2 pairs
                         float* __restrict__ out,
                         int e0, int total) {           // total = e0 + 2*e1
    const int gtid = blockIdx.x * blockDim.x + threadIdx.x;
    const int warp = gtid >> 5;
    const int lane = gtid & 31;
    const int pair = lane >> 1;   // 0..15
    const int h    = lane & 1;    // float4 half owned by this lane

    const int base = warp * DIST_PER_WARP + pair;

    // ---- phase 1: index loads (batched) ----
    int t[U], ia[U], ib[U];
    bool valid[U];
#pragma unroll
    for (int u = 0; u < U; u++) {
        int tt = base + u * 16;
        valid[u] = (tt < total);
        tt = valid[u] ? tt : (total - 1);      // clamp -> safe, converged
        t[u] = tt;
        const int2 p = (tt < e0) ? __ldg(v0 + tt)
                                 : __ldg(v1p + (tt - e0));
        ia[u] = p.x & IDX_MASK;
        ib[u] = p.y & IDX_MASK;
    }

    // ---- phase 2: gathers (batched; 8 independent LDG.128 in flight) ----
    float4 a[U], b[U];
#pragma unroll
    for (int u = 0; u < U; u++) {
        a[u] = __ldg(pts + ia[u] * DIM_F4 + h);
        b[u] = __ldg(pts + ib[u] * DIM_F4 + h);
    }

    // ---- phase 3: math + pair-combine + store ----
#pragma unroll
    for (int u = 0; u < U; u++) {
        float dx, s;
        dx = a[u].x - b[u].x; s = dx * dx;
        dx = a[u].y - b[u].y; s = fmaf(dx, dx, s);
        dx = a[u].z - b[u].z; s = fmaf(dx, dx, s);
        dx = a[u].w - b[u].w; s = fmaf(dx, dx, s);
        s += __shfl_xor_sync(0xFFFFFFFF, s, 1);
        if (valid[u] && h == 0)
            out[t[u]] = sqrtf(s);
    }
}

extern "C" void kernel_launch(void* const* d_in, const int* in_sizes, int n_in,
                              void* d_out, int out_size) {
    const float4* pts = (const float4*)d_in[0];
    const int2*   v0  = (const int2*)d_in[1];
    const int2*   v1p = (const int2*)d_in[2];
    float*        out = (float*)d_out;

    const int e0 = in_sizes[1] / 2;          // verts0 rows
    const int e1 = in_sizes[2] / 4;          // verts1 rows
    const int total = e0 + 2 * e1;           // flat distance count

    const int nwarps  = (total + DIST_PER_WARP - 1) / DIST_PER_WARP;
    const int threads = 256;
    const int blocks  = (nwarps * 32 + threads - 1) / threads;
    rips_pair_u4_kernel<<<blocks, threads>>>(pts, v0, v1p, out, e0, total);
}

// round 17
// speedup vs baseline: 1.0435x; 1.0290x over previous
#include <cuda_runtime.h>
#include <cstdint>

// RipsH1 edge-length gather — FINAL (R4 configuration, unchanged).
// Measured band of this exact binary across 8 runs:
//   35.3 / 35.7 / 36.4 / 36.4 / 36.9 / 36.9 / 37.0 / 37.3 us
//   (mean 36.5, sigma ~0.7 — "35.3" is the favorable tail, not a config)
//
// Flat distance list, D = e0 + 2*e1:
//   t <  e0 : (ia, ib) = verts0 row t
//   t >= e0 : (ia, ib) = ((int2*)verts1)[t - e0]
//   out[t]  = || pts[ia] - pts[ib] ||      (8-dim)
// (verts1 row j = [a0,b0,a1,b1]; out layout [deaths ++ dgm1-rowmajor] makes
//  the flat output index equal t exactly.)
//
// Evidence trail (R2-R16):
// - 2 lanes per distance: lane h owns float4 half h of each point; both 16B
//   halves of a 32B-aligned row share one sector -> ONE l1tex wavefront per
//   point (2/distance = structural minimum). R2->R3: 49.9 -> 39.6us.
// - U=4 distances per lane-pair, index loads then gathers front-batched
//   (8 independent LDG.128/lane). U-sweep: U=2 37.3, U=4 35.3, U=8 39.7us.
// - Natural regs (41) / ~56% occ: occupancy swept 33-87%, zero sensitivity.
// - Cache ops (.cg on streams AND gathers): measured neutral — L1% is
//   sector/replay processing throughput, not fill overhead.
// - Lane-split recheck: 8 LDGx(1+15*2.07)=256 vs 16 LDGx(1+7*2.07)=248 cyc
//   per 64 distances — 3% model delta, below run variance, costs extra SHFL.
// - Rejected on model: TMA tile::gather4 (tiny requests vs service cost),
//   smem two-pass binning (+80MB stream > savings), index dedup (same lines).
// - Operating point: ~90% of the l1tex uniform-random-gather floor; the
//   binding invariant (2 random 32B rows/distance) belongs to the problem.

static constexpr int DIM_F4   = 2;      // 8 floats = 2 float4
static constexpr int IDX_MASK = 0xFFFF; // N_POINTS = 65536 (power of two)
static constexpr int U        = 4;      // distances per lane-pair
static constexpr int DIST_PER_WARP = 16 * U;  // 64

__global__ __launch_bounds__(256)
void rips_pair_u4_kernel(const float4* __restrict__ pts,
                         const int2* __restrict__ v0,   // e0 rows of 2 i32
                         const int2* __restrict__ v1p,  // verts1 as 2*e1 int2 pairs
                         float* __restrict__ out,
                         int e0, int total) {           // total = e0 + 2*e1
    const int gtid = blockIdx.x * blockDim.x + threadIdx.x;
    const int warp = gtid >> 5;
    const int lane = gtid & 31;
    const int pair = lane >> 1;   // 0..15
    const int h    = lane & 1;    // float4 half owned by this lane

    const int base = warp * DIST_PER_WARP + pair;

    // ---- phase 1: index loads (batched) ----
    int t[U], ia[U], ib[U];
    bool valid[U];
#pragma unroll
    for (int u = 0; u < U; u++) {
        int tt = base + u * 16;
        valid[u] = (tt < total);
        tt = valid[u] ? tt : (total - 1);      // clamp -> safe, converged
        t[u] = tt;
        const int2 p = (tt < e0) ? __ldg(v0 + tt)
                                 : __ldg(v1p + (tt - e0));
        ia[u] = p.x & IDX_MASK;
        ib[u] = p.y & IDX_MASK;
    }

    // ---- phase 2: gathers (batched; 8 independent LDG.128 in flight) ----
    float4 a[U], b[U];
#pragma unroll
    for (int u = 0; u < U; u++) {
        a[u] = __ldg(pts + ia[u] * DIM_F4 + h);
        b[u] = __ldg(pts + ib[u] * DIM_F4 + h);
    }

    // ---- phase 3: math + pair-combine + store ----
#pragma unroll
    for (int u = 0; u < U; u++) {
        float dx, s;
        dx = a[u].x - b[u].x; s = dx * dx;
        dx = a[u].y - b[u].y; s = fmaf(dx, dx, s);
        dx = a[u].z - b[u].z; s = fmaf(dx, dx, s);
        dx = a[u].w - b[u].w; s = fmaf(dx, dx, s);
        s += __shfl_xor_sync(0xFFFFFFFF, s, 1);
        if (valid[u] && h == 0)
            out[t[u]] = sqrtf(s);
    }
}

extern "C" void kernel_launch(void* const* d_in, const int* in_sizes, int n_in,
                              void* d_out, int out_size) {
    const float4* pts = (const float4*)d_in[0];
    const int2*   v0  = (const int2*)d_in[1];
    const int2*   v1p = (const int2*)d_in[2];
    float*        out = (float*)d_out;

    const int e0 = in_sizes[1] / 2;          // verts0 rows
    const int e1 = in_sizes[2] / 4;          // verts1 rows
    const int total = e0 + 2 * e1;           // flat distance count

    const int nwarps  = (total + DIST_PER_WARP - 1) / DIST_PER_WARP;
    const int threads = 256;
    const int blocks  = (nwarps * 32 + threads - 1) / threads;
    rips_pair_u4_kernel<<<blocks, threads>>>(pts, v0, v1p, out, e0, total);
}